// round 16
// baseline (speedup 1.0000x reference)
#include <cuda_runtime.h>
#include <cuda_fp16.h>
#include <cstdint>

#define B 16
#define S 2048
#define D 64
#define TR 32
#define TC 128
#define NTH 512
#define KP 72          // halves pitch for pair-local K rows (144 B)
#define PP 2056        // halves pitch for dense compact P rows (4112 B)

// ---- smem byte offsets ----
#define OFF_PH    0                      // 32 x 2056 half = 131584
#define OFF_STAGE 131584                 // pair-private rings (K: 8x3x2304; V: 8x3x2048)
#define OFF_QH    186880                 // 4608
#define OFF_PINV  196096                 // 8192
#define OFF_WSUM  204288                 // 128
#define OFF_INV   204416                 // 128
#define OFF_ORIG  204544                 // 128
#define SMEM_BYTES 204672

#define KSTG(pair, stage) (OFF_STAGE + (pair) * 6912 + (stage) * 2304)
#define VSTG(pair, stage) (OFF_STAGE + (pair) * 6144 + (stage) * 2048)

// log2(e)/8 : folds the 1/sqrt(64) score scale AND exp->exp2 conversion into Q
#define QSCALE 0.18033688011112042f

// ---------- device scratch ----------
__device__ int g_cidx[B][S];
__device__ int g_midx[B][S];
__device__ int g_pinv[B][S];
__device__ int g_ccnt[B];
__device__ __half g_kh[(size_t)B * S * D];
__device__ __half g_vh[(size_t)B * S * D];

// ---------- asm helpers ----------
__device__ __forceinline__ void ldsm4(uint32_t& r0, uint32_t& r1, uint32_t& r2,
                                      uint32_t& r3, uint32_t a) {
    asm volatile("ldmatrix.sync.aligned.m8n8.x4.shared.b16 {%0,%1,%2,%3}, [%4];"
                 : "=r"(r0), "=r"(r1), "=r"(r2), "=r"(r3) : "r"(a));
}
__device__ __forceinline__ void ldsm2t(uint32_t& r0, uint32_t& r1, uint32_t a) {
    asm volatile("ldmatrix.sync.aligned.m8n8.x2.trans.shared.b16 {%0,%1}, [%2];"
                 : "=r"(r0), "=r"(r1) : "r"(a));
}
__device__ __forceinline__ void mma16816(float* d, uint32_t a0, uint32_t a1,
                                         uint32_t a2, uint32_t a3,
                                         uint32_t b0, uint32_t b1) {
    asm volatile(
        "mma.sync.aligned.m16n8k16.row.col.f32.f16.f16.f32 "
        "{%0,%1,%2,%3},{%4,%5,%6,%7},{%8,%9},{%0,%1,%2,%3};"
        : "+f"(d[0]), "+f"(d[1]), "+f"(d[2]), "+f"(d[3])
        : "r"(a0), "r"(a1), "r"(a2), "r"(a3), "r"(b0), "r"(b1));
}
__device__ __forceinline__ float ex2(float x) {
    float r;
    asm("ex2.approx.f32 %0, %1;" : "=f"(r) : "f"(x));
    return r;
}
__device__ __forceinline__ void cpa16(uint32_t saddr, const void* g) {
    asm volatile("cp.async.cg.shared.global [%0], [%1], 16;" :: "r"(saddr), "l"(g)
                 : "memory");
}
__device__ __forceinline__ void cpcommit() {
    asm volatile("cp.async.commit_group;" ::: "memory");
}
__device__ __forceinline__ void cpwait1() {
    asm volatile("cp.async.wait_group 1;" ::: "memory");
}
__device__ __forceinline__ void cpwait0() {
    asm volatile("cp.async.wait_group 0;" ::: "memory");
}
__device__ __forceinline__ void barpair(int id) {   // 2-warp named barrier
    asm volatile("bar.sync %0, 64;" :: "r"(id) : "memory");
}
// streaming store (evict-first): output never re-read; keep K/V resident in L2
__device__ __forceinline__ void stcs4(float4* p, float4 v) {
    asm volatile("st.global.cs.v4.f32 [%0], {%1,%2,%3,%4};"
                 :: "l"(p), "f"(v.x), "f"(v.y), "f"(v.z), "f"(v.w) : "memory");
}

// ---------- mask build ----------
__global__ void build_mask_kernel(const void* mptr) {
    const int b = blockIdx.x;
    const int tid = threadIdx.x;
    __shared__ int warpTot[8];
    __shared__ int okInt, okFlt;
    const unsigned char* pb = (const unsigned char*)mptr;
    if (tid == 0) { okInt = 1; okFlt = 1; }
    __syncthreads();
    {
        unsigned char b0 = pb[4*tid], b1 = pb[4*tid+1], b2 = pb[4*tid+2], b3 = pb[4*tid+3];
        bool gi = (b0 <= 1 && b1 == 0 && b2 == 0 && b3 == 0);
        bool zf = (b0 == 0 && b1 == 0 && b2 == 0 && b3 == 0);
        bool of = (b0 == 0 && b1 == 0 && b2 == 0x80 && b3 == 0x3f);
        if (!gi) atomicExch(&okInt, 0);
        if (!(zf || of)) atomicExch(&okFlt, 0);
    }
    __syncthreads();
    const int mode = okInt ? 1 : (okFlt ? 2 : 0);
    unsigned char mloc[8];
    int cnt = 0;
    #pragma unroll
    for (int k = 0; k < 8; k++) {
        int i = b * S + tid * 8 + k;
        unsigned char m;
        if (mode == 1)      m = (((const int*)mptr)[i] != 0);
        else if (mode == 2) m = (((const float*)mptr)[i] != 0.0f);
        else                m = (pb[i] != 0);
        mloc[k] = m;
        cnt += (m == 0);
    }
    int lane = tid & 31, w = tid >> 5;
    int x = cnt;
    #pragma unroll
    for (int off = 1; off < 32; off <<= 1) {
        int y = __shfl_up_sync(0xffffffffu, x, off);
        if (lane >= off) x += y;
    }
    if (lane == 31) warpTot[w] = x;
    __syncthreads();
    int wOff = 0;
    for (int ww = 0; ww < w; ww++) wOff += warpTot[ww];
    int pos = wOff + x - cnt;
    #pragma unroll
    for (int k = 0; k < 8; k++) {
        int idx = tid * 8 + k;
        if (!mloc[k]) {
            g_cidx[b][pos] = idx;
            g_pinv[b][idx] = pos;
            pos++;
        } else {
            g_midx[b][idx - pos] = idx;
            g_pinv[b][idx] = -1;
        }
    }
    if (tid == 255) g_ccnt[b] = pos;
}

// ---------- preprocess K -> fp16 in compact order ----------
__global__ void preprocess_k_kernel(const float* __restrict__ K) {
    const int b = blockIdx.y;
    const int tid = threadIdx.x;
    const int cc = blockIdx.x * 64 + (tid >> 2);
    const int qd = (tid & 3) * 16;
    const int nc = g_ccnt[b];
    __half* kh = g_kh + ((size_t)b * S + cc) * D + qd;
    if (cc < nc) {
        int orig = g_cidx[b][cc];
        const float4* kp = (const float4*)(K + ((size_t)b * S + orig) * D + qd);
        #pragma unroll
        for (int j = 0; j < 4; j++) {
            float4 kv = kp[j];
            ((__half2*)(kh + j * 4))[0] = __floats2half2_rn(kv.x, kv.y);
            ((__half2*)(kh + j * 4))[1] = __floats2half2_rn(kv.z, kv.w);
        }
    } else {
        uint2 z = {0u, 0u};
        #pragma unroll
        for (int j = 0; j < 4; j++) *(uint2*)(kh + j * 4) = z;
    }
}

// ---------- preprocess V -> fp16 in compact order ----------
__global__ void preprocess_v_kernel(const float* __restrict__ V) {
    const int b = blockIdx.y;
    const int tid = threadIdx.x;
    const int cc = blockIdx.x * 64 + (tid >> 2);
    const int qd = (tid & 3) * 16;
    const int nc = g_ccnt[b];
    __half* vh = g_vh + ((size_t)b * S + cc) * D + qd;
    if (cc < nc) {
        int orig = g_cidx[b][cc];
        const float4* vp = (const float4*)(V + ((size_t)b * S + orig) * D + qd);
        #pragma unroll
        for (int j = 0; j < 4; j++) {
            float4 vv = vp[j];
            ((__half2*)(vh + j * 4))[0] = __floats2half2_rn(vv.x, vv.y);
            ((__half2*)(vh + j * 4))[1] = __floats2half2_rn(vv.z, vv.w);
        }
    } else {
        uint2 z = {0u, 0u};
        #pragma unroll
        for (int j = 0; j < 4; j++) *(uint2*)(vh + j * 4) = z;
    }
}

// ---------- main attention kernel ----------
extern __shared__ char smem[];

__global__ __launch_bounds__(NTH, 1)
void attn_kernel(const float* __restrict__ Q, float* __restrict__ out) {
    const int b = blockIdx.y;
    const int ncols = g_ccnt[b];
    const int nActive = (ncols + TR - 1) / TR;
    const int tid = threadIdx.x;

    // ---- zero-fill branch: masked rows ----
    if ((int)blockIdx.x >= nActive) {
        const int nmask = S - ncols;
        const int m0 = ((int)blockIdx.x - nActive) * TR;
        const int r = tid >> 4, tg = tid & 15;
        if (m0 + r >= nmask) return;
        const int row = g_midx[b][m0 + r];
        float4 z = {0.f, 0.f, 0.f, 0.f};
        float4* arow = (float4*)(out + (size_t)B * S * D + ((size_t)b * S + row) * S);
        #pragma unroll 8
        for (int it = 0; it < 32; it++) stcs4(arow + it * 16 + tg, z);
        stcs4((float4*)(out + ((size_t)b * S + row) * D + tg * 4), z);
        return;
    }

    const int row0c = blockIdx.x * TR;
    const int nrows = min(TR, ncols - row0c);
    const int lane = tid & 31, w = tid >> 5;
    const int rg = w >> 3, cg = w & 7;
    const bool prod = (rg == 0);
    const int nt = (ncols + TC - 1) / TC;

    __half* sPh  = (__half*)(smem + OFF_PH);
    int*    sPinv= (int*)(smem + OFF_PINV);
    float*  sWsum= (float*)(smem + OFF_WSUM);
    float*  sInv = (float*)(smem + OFF_INV);
    int*    sOrig= (int*)(smem + OFF_ORIG);
    const uint32_t smemBase = (uint32_t)__cvta_generic_to_shared(smem);

    const __half* khB = g_kh + (size_t)b * S * D;
    const __half* vhB = g_vh + (size_t)b * S * D;

    // ---- phase-1 prologue: producer warps prefetch their K slices, tiles 0,1 ----
    if (prod) {
        #pragma unroll
        for (int t = 0; t < 2; t++) {
            if (t < nt) {
                uint32_t kb = smemBase + (uint32_t)KSTG(cg, t);
                #pragma unroll
                for (int u = 0; u < 4; u++) {
                    int chunk = lane + 32 * u;          // 0..127
                    int row = chunk >> 3, cc = chunk & 7;
                    cpa16(kb + (uint32_t)((row * KP + cc * 8) * 2),
                          khB + (size_t)(t * TC + cg * 16 + row) * D + cc * 8);
                }
            }
            cpcommit();
        }
    }

    if (tid < TR) sWsum[tid] = 0.f;
    ((int4*)sPinv)[tid] = ((const int4*)&g_pinv[b][0])[tid];

    // ---- Q load -> fp16 (pre-scaled by log2e/8) ----
    {
        int r = tid >> 4, f = tid & 15;
        float4 q = {0.f, 0.f, 0.f, 0.f};
        if (r < nrows) {
            int orig = g_cidx[b][row0c + r];
            if (f == 0) sOrig[r] = orig;
            q = ((const float4*)(Q + ((size_t)b * S + orig) * D))[f];
            q.x *= QSCALE; q.y *= QSCALE; q.z *= QSCALE; q.w *= QSCALE;
        }
        __half2* dh = (__half2*)(smem + OFF_QH + ((size_t)r * KP + f * 4) * 2);
        dh[0] = __floats2half2_rn(q.x, q.y);
        dh[1] = __floats2half2_rn(q.z, q.w);
    }
    __syncthreads();

    // ---- Q fragments to registers ----
    uint32_t qh[4][4];
    {
        const uint32_t aQoff =
            (uint32_t)(((rg * 16 + (lane & 15)) * KP + ((lane >> 4) << 3)) * 2);
        #pragma unroll
        for (int kk = 0; kk < 4; kk++)
            ldsm4(qh[kk][0], qh[kk][1], qh[kk][2], qh[kk][3],
                  smemBase + OFF_QH + aQoff + kk * 32);
    }

    // pair-local K fragment base (16 rows x 128B, KP pitch)
    const uint32_t bKloc =
        (uint32_t)((((lane & 7) + ((lane >> 4) << 3)) * KP
                    + (((lane >> 3) & 1) << 3)) * 2);
    const int rowE = rg * 16 + (lane >> 2);
    const int colE = cg * 16 + ((lane & 3) << 1);
    const int barid = cg + 1;

    float sumLo = 0.f, sumHi = 0.f;

    // ================= PHASE 1: QK + deferred-exp, pair-private pipeline =======
    {
        float p0[4], p1[4];
        int cbPrev = 0;
        for (int i = 0; i < nt; i++) {
            const int ct = i * TC;
            const uint32_t kb = smemBase + (uint32_t)KSTG(cg, i % 3);
            if (prod) cpwait1();
            barpair(barid);

            float c0[4] = {0.f, 0.f, 0.f, 0.f};
            float c1[4] = {0.f, 0.f, 0.f, 0.f};
            #pragma unroll
            for (int kk = 0; kk < 4; kk++) {
                uint32_t bh0, bh1, bh2, bh3;
                ldsm4(bh0, bh1, bh2, bh3, kb + bKloc + kk * 32);
                mma16816(c0, qh[kk][0], qh[kk][1], qh[kk][2], qh[kk][3], bh0, bh1);
                mma16816(c1, qh[kk][0], qh[kk][1], qh[kk][2], qh[kk][3], bh2, bh3);
            }
            if (prod) {
                if (i + 2 < nt) {
                    uint32_t kd = smemBase + (uint32_t)KSTG(cg, (i + 2) % 3);
                    #pragma unroll
                    for (int u = 0; u < 4; u++) {
                        int chunk = lane + 32 * u;
                        int row = chunk >> 3, cc = chunk & 7;
                        cpa16(kd + (uint32_t)((row * KP + cc * 8) * 2),
                              khB + (size_t)((i + 2) * TC + cg * 16 + row) * D + cc * 8);
                    }
                }
                cpcommit();
            }
            if (i > 0) {
                const int cb = cbPrev;
                float e0 = (cb     < ncols) ? ex2(p0[0]) : 0.f;
                float e1 = (cb + 1 < ncols) ? ex2(p0[1]) : 0.f;
                float e2 = (cb     < ncols) ? ex2(p0[2]) : 0.f;
                float e3 = (cb + 1 < ncols) ? ex2(p0[3]) : 0.f;
                float e4 = (cb + 8 < ncols) ? ex2(p1[0]) : 0.f;
                float e5 = (cb + 9 < ncols) ? ex2(p1[1]) : 0.f;
                float e6 = (cb + 8 < ncols) ? ex2(p1[2]) : 0.f;
                float e7 = (cb + 9 < ncols) ? ex2(p1[3]) : 0.f;
                sumLo += (e0 + e1) + (e4 + e5);
                sumHi += (e2 + e3) + (e6 + e7);
                *(__half2*)&sPh[rowE * PP + cb]           = __floats2half2_rn(e0, e1);
                *(__half2*)&sPh[(rowE + 8) * PP + cb]     = __floats2half2_rn(e2, e3);
                *(__half2*)&sPh[rowE * PP + cb + 8]       = __floats2half2_rn(e4, e5);
                *(__half2*)&sPh[(rowE + 8) * PP + cb + 8] = __floats2half2_rn(e6, e7);
            }
            #pragma unroll
            for (int j = 0; j < 4; j++) { p0[j] = c0[j]; p1[j] = c1[j]; }
            cbPrev = ct + colE;
        }
        {
            const int cb = cbPrev;
            float e0 = (cb     < ncols) ? ex2(p0[0]) : 0.f;
            float e1 = (cb + 1 < ncols) ? ex2(p0[1]) : 0.f;
            float e2 = (cb     < ncols) ? ex2(p0[2]) : 0.f;
            float e3 = (cb + 1 < ncols) ? ex2(p0[3]) : 0.f;
            float e4 = (cb + 8 < ncols) ? ex2(p1[0]) : 0.f;
            float e5 = (cb + 9 < ncols) ? ex2(p1[1]) : 0.f;
            float e6 = (cb + 8 < ncols) ? ex2(p1[2]) : 0.f;
            float e7 = (cb + 9 < ncols) ? ex2(p1[3]) : 0.f;
            sumLo += (e0 + e1) + (e4 + e5);
            sumHi += (e2 + e3) + (e6 + e7);
            *(__half2*)&sPh[rowE * PP + cb]           = __floats2half2_rn(e0, e1);
            *(__half2*)&sPh[(rowE + 8) * PP + cb]     = __floats2half2_rn(e2, e3);
            *(__half2*)&sPh[rowE * PP + cb + 8]       = __floats2half2_rn(e4, e5);
            *(__half2*)&sPh[(rowE + 8) * PP + cb + 8] = __floats2half2_rn(e6, e7);
        }
    }

    // ---- row sums -> sInv (block-wide) ----
    sumLo += __shfl_xor_sync(0xffffffffu, sumLo, 1);
    sumLo += __shfl_xor_sync(0xffffffffu, sumLo, 2);
    sumHi += __shfl_xor_sync(0xffffffffu, sumHi, 1);
    sumHi += __shfl_xor_sync(0xffffffffu, sumHi, 2);
    if ((lane & 3) == 0) {
        atomicAdd(&sWsum[rowE], sumLo);
        atomicAdd(&sWsum[rowE + 8], sumHi);
    }
    __syncthreads();
    if (tid < TR) {
        float t = sWsum[tid];
        sInv[tid] = (t > 0.f) ? (1.f / t) : 0.f;
    }
    __syncthreads();

    // ================= PHASE 2: V prologue -> WB -> pair-private PV ============
    if (prod) {
        cpwait0();   // drain stale K groups, reset count
        #pragma unroll
        for (int t = 0; t < 2; t++) {
            if (t < nt) {
                uint32_t vb = smemBase + (uint32_t)VSTG(cg, t);
                #pragma unroll
                for (int u = 0; u < 4; u++) {
                    int row = lane + 32 * u;            // 0..127
                    cpa16(vb + (uint32_t)(row * 16),
                          vhB + (size_t)(t * TC + row) * D + cg * 8);
                }
            }
            cpcommit();
        }
    }

    // ---- attn writeback: 2 rows/warp, pinv loaded once per column group ----
    {
        const int r0 = w * 2;
        const bool ok0 = (r0 < nrows), ok1 = (r0 + 1 < nrows);
        const float inv0 = ok0 ? sInv[r0] : 0.f;
        const float inv1 = ok1 ? sInv[r0 + 1] : 0.f;
        const __half* prow0 = &sPh[r0 * PP];
        const __half* prow1 = &sPh[(r0 + 1) * PP];
        float4* dst0 = ok0 ? (float4*)(out + (size_t)B * S * D
                                        + ((size_t)b * S + sOrig[r0]) * S) : nullptr;
        float4* dst1 = ok1 ? (float4*)(out + (size_t)B * S * D
                                        + ((size_t)b * S + sOrig[r0 + 1]) * S) : nullptr;
        if (ok0) {
            #pragma unroll 4
            for (int it = 0; it < 16; it++) {
                int cb = it * 32 + lane;
                int4 pv = ((const int4*)sPinv)[cb];
                float4 o0, o1;
                o0.x = (pv.x >= 0) ? __half2float(prow0[pv.x]) * inv0 : 0.f;
                o0.y = (pv.y >= 0) ? __half2float(prow0[pv.y]) * inv0 : 0.f;
                o0.z = (pv.z >= 0) ? __half2float(prow0[pv.z]) * inv0 : 0.f;
                o0.w = (pv.w >= 0) ? __half2float(prow0[pv.w]) * inv0 : 0.f;
                if (ok1) {
                    o1.x = (pv.x >= 0) ? __half2float(prow1[pv.x]) * inv1 : 0.f;
                    o1.y = (pv.y >= 0) ? __half2float(prow1[pv.y]) * inv1 : 0.f;
                    o1.z = (pv.z >= 0) ? __half2float(prow1[pv.z]) * inv1 : 0.f;
                    o1.w = (pv.w >= 0) ? __half2float(prow1[pv.w]) * inv1 : 0.f;
                }
                stcs4(dst0 + cb, o0);
                if (ok1) stcs4(dst1 + cb, o1);
            }
        }
    }

    // ---- PV: pair-private V slices, named-barrier pipeline ----
    {
        const uint32_t aP =
            (uint32_t)(((rg * 16 + (lane & 15)) * PP + ((lane >> 4) << 3)) * 2);
        const uint32_t vloc = (uint32_t)((lane & 15) * 16);
        const int colW = cg * 8 + ((lane & 3) << 1);

        float ctx[4] = {0.f, 0.f, 0.f, 0.f};

        for (int i = 0; i < nt; i++) {
            const int ct = i * TC;
            const uint32_t vb = smemBase + (uint32_t)VSTG(cg, i % 3);
            if (prod) cpwait1();
            barpair(barid);
            #pragma unroll
            for (int ks = 0; ks < 8; ks++) {
                uint32_t a0, a1, a2, a3, b0, b1;
                ldsm2t(b0, b1, vb + vloc + (uint32_t)(ks * 256));
                ldsm4(a0, a1, a2, a3,
                      smemBase + OFF_PH + aP + (uint32_t)((ct + ks * 16) * 2));
                mma16816(ctx, a0, a1, a2, a3, b0, b1);
            }
            if (prod) {
                if (i + 2 < nt) {
                    uint32_t vd = smemBase + (uint32_t)VSTG(cg, (i + 2) % 3);
                    #pragma unroll
                    for (int u = 0; u < 4; u++) {
                        int row = lane + 32 * u;
                        cpa16(vd + (uint32_t)(row * 16),
                              vhB + (size_t)((i + 2) * TC + row) * D + cg * 8);
                    }
                }
                cpcommit();
            }
        }
        // ---- context write ----
        {
            const int r0 = rg * 16 + (lane >> 2);
            if (r0 < nrows) {
                float inv = sInv[r0];
                *(float2*)(out + ((size_t)b * S + sOrig[r0]) * D + colW) =
                    make_float2(ctx[0] * inv, ctx[1] * inv);
            }
            if (r0 + 8 < nrows) {
                float inv = sInv[r0 + 8];
                *(float2*)(out + ((size_t)b * S + sOrig[r0 + 8]) * D + colW) =
                    make_float2(ctx[2] * inv, ctx[3] * inv);
            }
        }
    }
}

extern "C" void kernel_launch(void* const* d_in, const int* in_sizes, int n_in,
                              void* d_out, int out_size) {
    const float* Q = (const float*)d_in[0];
    const float* K = (const float*)d_in[1];
    const float* V = (const float*)d_in[2];
    const void*  M = d_in[3];
    float* out = (float*)d_out;

    cudaFuncSetAttribute(attn_kernel, cudaFuncAttributeMaxDynamicSharedMemorySize,
                         SMEM_BYTES);

    build_mask_kernel<<<B, 256>>>(M);
    preprocess_k_kernel<<<dim3(S / 64, B), 256>>>(K);
    preprocess_v_kernel<<<dim3(S / 64, B), 256>>>(V);
    attn_kernel<<<dim3(S / TR + 1, B), NTH, SMEM_BYTES>>>(Q, out);
}

// round 17
// speedup vs baseline: 1.0514x; 1.0514x over previous
#include <cuda_runtime.h>
#include <cuda_fp16.h>
#include <cstdint>

#define B 16
#define S 2048
#define D 64
#define TR 32
#define TC 128
#define NTH 512
#define KP 72          // halves pitch for K/V smem rows (144 B, ldsm conflict-free)
#define PP 2056        // halves pitch for dense compact P rows (4112 B)

// ---- smem byte offsets ----
#define OFF_PH    0                      // 32 x 2056 half = 131584
#define OFF_STAGE 131584                 // 2 stages x 36864 (K @ +0, V @ +18432)
#define STG_STRIDE 36864
#define STG_V     18432
#define OFF_QH    205312                 // 4608
#define OFF_PINV  209920                 // 8192
#define OFF_WSUM  218112                 // 128
#define OFF_INV   218240                 // 128
#define OFF_ORIG  218368                 // 128
#define SMEM_BYTES 218496

// log2(e)/8 : folds the 1/sqrt(64) score scale AND exp->exp2 conversion into Q
#define QSCALE 0.18033688011112042f

// ---------- device scratch ----------
__device__ int g_cidx[B][S];
__device__ int g_midx[B][S];
__device__ int g_pinv[B][S];
__device__ int g_ccnt[B];
__device__ __half g_kh[(size_t)B * S * D];
__device__ __half g_vh[(size_t)B * S * D];

// ---------- asm helpers ----------
__device__ __forceinline__ void ldsm4(uint32_t& r0, uint32_t& r1, uint32_t& r2,
                                      uint32_t& r3, uint32_t a) {
    asm volatile("ldmatrix.sync.aligned.m8n8.x4.shared.b16 {%0,%1,%2,%3}, [%4];"
                 : "=r"(r0), "=r"(r1), "=r"(r2), "=r"(r3) : "r"(a));
}
__device__ __forceinline__ void ldsm2t(uint32_t& r0, uint32_t& r1, uint32_t a) {
    asm volatile("ldmatrix.sync.aligned.m8n8.x2.trans.shared.b16 {%0,%1}, [%2];"
                 : "=r"(r0), "=r"(r1) : "r"(a));
}
__device__ __forceinline__ void mma16816(float* d, uint32_t a0, uint32_t a1,
                                         uint32_t a2, uint32_t a3,
                                         uint32_t b0, uint32_t b1) {
    asm volatile(
        "mma.sync.aligned.m16n8k16.row.col.f32.f16.f16.f32 "
        "{%0,%1,%2,%3},{%4,%5,%6,%7},{%8,%9},{%0,%1,%2,%3};"
        : "+f"(d[0]), "+f"(d[1]), "+f"(d[2]), "+f"(d[3])
        : "r"(a0), "r"(a1), "r"(a2), "r"(a3), "r"(b0), "r"(b1));
}
__device__ __forceinline__ void mma16808(float* d, uint32_t a0, uint32_t a1,
                                         uint32_t b0) {
    asm volatile(
        "mma.sync.aligned.m16n8k8.row.col.f32.f16.f16.f32 "
        "{%0,%1,%2,%3},{%4,%5},{%6},{%0,%1,%2,%3};"
        : "+f"(d[0]), "+f"(d[1]), "+f"(d[2]), "+f"(d[3])
        : "r"(a0), "r"(a1), "r"(b0));
}
__device__ __forceinline__ float ex2(float x) {
    float r;
    asm("ex2.approx.f32 %0, %1;" : "=f"(r) : "f"(x));
    return r;
}
__device__ __forceinline__ void cpa16(uint32_t saddr, const void* g) {
    asm volatile("cp.async.cg.shared.global [%0], [%1], 16;" :: "r"(saddr), "l"(g)
                 : "memory");
}
__device__ __forceinline__ void cpcommit() {
    asm volatile("cp.async.commit_group;" ::: "memory");
}
__device__ __forceinline__ void cpwait1() {
    asm volatile("cp.async.wait_group 1;" ::: "memory");
}
__device__ __forceinline__ void cpwait0() {
    asm volatile("cp.async.wait_group 0;" ::: "memory");
}
// streaming store (evict-first): output never re-read; keep K/V resident in L2
__device__ __forceinline__ void stcs4(float4* p, float4 v) {
    asm volatile("st.global.cs.v4.f32 [%0], {%1,%2,%3,%4};"
                 :: "l"(p), "f"(v.x), "f"(v.y), "f"(v.z), "f"(v.w) : "memory");
}

// ---------- mask build ----------
__global__ void build_mask_kernel(const void* mptr) {
    const int b = blockIdx.x;
    const int tid = threadIdx.x;
    __shared__ int warpTot[8];
    __shared__ int okInt, okFlt;
    const unsigned char* pb = (const unsigned char*)mptr;
    if (tid == 0) { okInt = 1; okFlt = 1; }
    __syncthreads();
    {
        unsigned char b0 = pb[4*tid], b1 = pb[4*tid+1], b2 = pb[4*tid+2], b3 = pb[4*tid+3];
        bool gi = (b0 <= 1 && b1 == 0 && b2 == 0 && b3 == 0);
        bool zf = (b0 == 0 && b1 == 0 && b2 == 0 && b3 == 0);
        bool of = (b0 == 0 && b1 == 0 && b2 == 0x80 && b3 == 0x3f);
        if (!gi) atomicExch(&okInt, 0);
        if (!(zf || of)) atomicExch(&okFlt, 0);
    }
    __syncthreads();
    const int mode = okInt ? 1 : (okFlt ? 2 : 0);
    unsigned char mloc[8];
    int cnt = 0;
    #pragma unroll
    for (int k = 0; k < 8; k++) {
        int i = b * S + tid * 8 + k;
        unsigned char m;
        if (mode == 1)      m = (((const int*)mptr)[i] != 0);
        else if (mode == 2) m = (((const float*)mptr)[i] != 0.0f);
        else                m = (pb[i] != 0);
        mloc[k] = m;
        cnt += (m == 0);
    }
    int lane = tid & 31, w = tid >> 5;
    int x = cnt;
    #pragma unroll
    for (int off = 1; off < 32; off <<= 1) {
        int y = __shfl_up_sync(0xffffffffu, x, off);
        if (lane >= off) x += y;
    }
    if (lane == 31) warpTot[w] = x;
    __syncthreads();
    int wOff = 0;
    for (int ww = 0; ww < w; ww++) wOff += warpTot[ww];
    int pos = wOff + x - cnt;
    #pragma unroll
    for (int k = 0; k < 8; k++) {
        int idx = tid * 8 + k;
        if (!mloc[k]) {
            g_cidx[b][pos] = idx;
            g_pinv[b][idx] = pos;
            pos++;
        } else {
            g_midx[b][idx - pos] = idx;
            g_pinv[b][idx] = -1;
        }
    }
    if (tid == 255) g_ccnt[b] = pos;
}

// ---------- preprocess K -> fp16 in compact order ----------
__global__ void preprocess_k_kernel(const float* __restrict__ K) {
    const int b = blockIdx.y;
    const int tid = threadIdx.x;
    const int cc = blockIdx.x * 64 + (tid >> 2);
    const int qd = (tid & 3) * 16;
    const int nc = g_ccnt[b];
    __half* kh = g_kh + ((size_t)b * S + cc) * D + qd;
    if (cc < nc) {
        int orig = g_cidx[b][cc];
        const float4* kp = (const float4*)(K + ((size_t)b * S + orig) * D + qd);
        #pragma unroll
        for (int j = 0; j < 4; j++) {
            float4 kv = kp[j];
            ((__half2*)(kh + j * 4))[0] = __floats2half2_rn(kv.x, kv.y);
            ((__half2*)(kh + j * 4))[1] = __floats2half2_rn(kv.z, kv.w);
        }
    } else {
        uint2 z = {0u, 0u};
        #pragma unroll
        for (int j = 0; j < 4; j++) *(uint2*)(kh + j * 4) = z;
    }
}

// ---------- preprocess V -> fp16 in compact order ----------
__global__ void preprocess_v_kernel(const float* __restrict__ V) {
    const int b = blockIdx.y;
    const int tid = threadIdx.x;
    const int cc = blockIdx.x * 64 + (tid >> 2);
    const int qd = (tid & 3) * 16;
    const int nc = g_ccnt[b];
    __half* vh = g_vh + ((size_t)b * S + cc) * D + qd;
    if (cc < nc) {
        int orig = g_cidx[b][cc];
        const float4* vp = (const float4*)(V + ((size_t)b * S + orig) * D + qd);
        #pragma unroll
        for (int j = 0; j < 4; j++) {
            float4 vv = vp[j];
            ((__half2*)(vh + j * 4))[0] = __floats2half2_rn(vv.x, vv.y);
            ((__half2*)(vh + j * 4))[1] = __floats2half2_rn(vv.z, vv.w);
        }
    } else {
        uint2 z = {0u, 0u};
        #pragma unroll
        for (int j = 0; j < 4; j++) *(uint2*)(vh + j * 4) = z;
    }
}

// ---------- main attention kernel (fused QK->exp->PV, single pass) ----------
extern __shared__ char smem[];

__global__ __launch_bounds__(NTH, 1)
void attn_kernel(const float* __restrict__ Q, float* __restrict__ out) {
    const int b = blockIdx.y;
    const int ncols = g_ccnt[b];
    const int nActive = (ncols + TR - 1) / TR;
    const int tid = threadIdx.x;

    // ---- zero-fill branch: masked rows ----
    if ((int)blockIdx.x >= nActive) {
        const int nmask = S - ncols;
        const int m0 = ((int)blockIdx.x - nActive) * TR;
        const int r = tid >> 4, tg = tid & 15;
        if (m0 + r >= nmask) return;
        const int row = g_midx[b][m0 + r];
        float4 z = {0.f, 0.f, 0.f, 0.f};
        float4* arow = (float4*)(out + (size_t)B * S * D + ((size_t)b * S + row) * S);
        #pragma unroll 8
        for (int it = 0; it < 32; it++) stcs4(arow + it * 16 + tg, z);
        stcs4((float4*)(out + ((size_t)b * S + row) * D + tg * 4), z);
        return;
    }

    const int row0c = blockIdx.x * TR;
    const int nrows = min(TR, ncols - row0c);
    const int lane = tid & 31, w = tid >> 5;
    const int rg = w >> 3, cg = w & 7;
    const int nt = (ncols + TC - 1) / TC;

    __half* sPh  = (__half*)(smem + OFF_PH);
    int*    sPinv= (int*)(smem + OFF_PINV);
    float*  sWsum= (float*)(smem + OFF_WSUM);
    float*  sInv = (float*)(smem + OFF_INV);
    int*    sOrig= (int*)(smem + OFF_ORIG);
    const uint32_t smemBase = (uint32_t)__cvta_generic_to_shared(smem);

    const __half* khB = g_kh + (size_t)b * S * D;
    const __half* vhB = g_vh + (size_t)b * S * D;

    // ---- prologue: prefetch K+V tiles 0,1 (2-stage ring) ----
    {
        const int j = tid >> 2, c = (tid & 3) * 2;
        #pragma unroll
        for (int t = 0; t < 2; t++) {
            if (t < nt) {
                uint32_t stg = smemBase + OFF_STAGE + t * STG_STRIDE
                             + (uint32_t)((j * KP + c * 8) * 2);
                size_t gofs = (size_t)(t * TC + j) * D + c * 8;
                cpa16(stg, khB + gofs);
                cpa16(stg + 16, khB + gofs + 8);
                cpa16(stg + STG_V, vhB + gofs);
                cpa16(stg + STG_V + 16, vhB + gofs + 8);
            }
            cpcommit();
        }
    }

    if (tid < TR) sWsum[tid] = 0.f;
    ((int4*)sPinv)[tid] = ((const int4*)&g_pinv[b][0])[tid];

    // ---- Q load -> fp16 (pre-scaled by log2e/8) ----
    {
        int r = tid >> 4, f = tid & 15;
        float4 q = {0.f, 0.f, 0.f, 0.f};
        if (r < nrows) {
            int orig = g_cidx[b][row0c + r];
            if (f == 0) sOrig[r] = orig;
            q = ((const float4*)(Q + ((size_t)b * S + orig) * D))[f];
            q.x *= QSCALE; q.y *= QSCALE; q.z *= QSCALE; q.w *= QSCALE;
        }
        __half2* dh = (__half2*)(smem + OFF_QH + ((size_t)r * KP + f * 4) * 2);
        dh[0] = __floats2half2_rn(q.x, q.y);
        dh[1] = __floats2half2_rn(q.z, q.w);
    }
    __syncthreads();

    // ---- Q fragments to registers ----
    uint32_t qh[4][4];
    {
        const uint32_t aQoff =
            (uint32_t)(((rg * 16 + (lane & 15)) * KP + ((lane >> 4) << 3)) * 2);
        #pragma unroll
        for (int kk = 0; kk < 4; kk++)
            ldsm4(qh[kk][0], qh[kk][1], qh[kk][2], qh[kk][3],
                  smemBase + OFF_QH + aQoff + kk * 32);
    }

    const uint32_t bKoff =
        (uint32_t)(((cg * 16 + (lane & 7) + ((lane >> 4) << 3)) * KP
                    + (((lane >> 3) & 1) << 3)) * 2);
    // V B-frag base: this warp's 16 V rows (cg*16..+16), per n-tile +16B
    const uint32_t bVoff =
        (uint32_t)(((cg * 16 + (lane & 15)) * KP) * 2);
    const int rowE = rg * 16 + (lane >> 2);
    const int colE = cg * 16 + ((lane & 3) << 1);

    float sumLo = 0.f, sumHi = 0.f;
    float ctx[8][4];
    #pragma unroll
    for (int n = 0; n < 8; n++)
        ctx[n][0] = ctx[n][1] = ctx[n][2] = ctx[n][3] = 0.f;

    // ================= fused tile loop: QK -> exp -> PV ========================
    for (int i = 0; i < nt; i++) {
        const int ct = i * TC;
        const uint32_t stg = smemBase + OFF_STAGE + (uint32_t)((i & 1) * STG_STRIDE);
        cpwait1();
        __syncthreads();

        // ---- QK: C = Q(16xD) * K^T strip (16 cols) ----
        float c0[4] = {0.f, 0.f, 0.f, 0.f};
        float c1[4] = {0.f, 0.f, 0.f, 0.f};
        #pragma unroll
        for (int kk = 0; kk < 4; kk++) {
            uint32_t bh0, bh1, bh2, bh3;
            ldsm4(bh0, bh1, bh2, bh3, stg + bKoff + kk * 32);
            mma16816(c0, qh[kk][0], qh[kk][1], qh[kk][2], qh[kk][3], bh0, bh1);
            mma16816(c1, qh[kk][0], qh[kk][1], qh[kk][2], qh[kk][3], bh2, bh3);
        }

        // ---- exp + pack A-frags + STS P + row sums ----
        const int cb = ct + colE;
        float e0 = (cb     < ncols) ? ex2(c0[0]) : 0.f;
        float e1 = (cb + 1 < ncols) ? ex2(c0[1]) : 0.f;
        float e2 = (cb     < ncols) ? ex2(c0[2]) : 0.f;
        float e3 = (cb + 1 < ncols) ? ex2(c0[3]) : 0.f;
        float e4 = (cb + 8 < ncols) ? ex2(c1[0]) : 0.f;
        float e5 = (cb + 9 < ncols) ? ex2(c1[1]) : 0.f;
        float e6 = (cb + 8 < ncols) ? ex2(c1[2]) : 0.f;
        float e7 = (cb + 9 < ncols) ? ex2(c1[3]) : 0.f;
        sumLo += (e0 + e1) + (e4 + e5);
        sumHi += (e2 + e3) + (e6 + e7);
        __half2 h00 = __floats2half2_rn(e0, e1);   // A-frag kb0: row r
        __half2 h01 = __floats2half2_rn(e2, e3);   // A-frag kb0: row r+8
        __half2 h10 = __floats2half2_rn(e4, e5);   // A-frag kb1: row r
        __half2 h11 = __floats2half2_rn(e6, e7);   // A-frag kb1: row r+8
        *(__half2*)&sPh[rowE * PP + cb]           = h00;
        *(__half2*)&sPh[(rowE + 8) * PP + cb]     = h01;
        *(__half2*)&sPh[rowE * PP + cb + 8]       = h10;
        *(__half2*)&sPh[(rowE + 8) * PP + cb + 8] = h11;
        const uint32_t a00 = *(uint32_t*)&h00, a01 = *(uint32_t*)&h01;
        const uint32_t a10 = *(uint32_t*)&h10, a11 = *(uint32_t*)&h11;

        // ---- PV: ctx += P_strip(16x16) * V_strip(16x64), register A-frags ----
        #pragma unroll
        for (int n = 0; n < 8; n++) {
            uint32_t vb0, vb1;
            ldsm2t(vb0, vb1, stg + STG_V + bVoff + (uint32_t)(n * 16));
            mma16808(ctx[n], a00, a01, vb0);
            mma16808(ctx[n], a10, a11, vb1);
        }
        __syncthreads();   // stage (i&1) fully consumed

        // ---- prefetch K+V tile i+2 into stage (i&1) ----
        if (i + 2 < nt) {
            const int j = tid >> 2, cch = (tid & 3) * 2;
            uint32_t sdst = smemBase + OFF_STAGE + (uint32_t)((i & 1) * STG_STRIDE)
                          + (uint32_t)((j * KP + cch * 8) * 2);
            size_t gofs = (size_t)((i + 2) * TC + j) * D + cch * 8;
            cpa16(sdst, khB + gofs);
            cpa16(sdst + 16, khB + gofs + 8);
            cpa16(sdst + STG_V, vhB + gofs);
            cpa16(sdst + STG_V + 16, vhB + gofs + 8);
        }
        cpcommit();
    }

    // ---- row sums -> sInv ----
    sumLo += __shfl_xor_sync(0xffffffffu, sumLo, 1);
    sumLo += __shfl_xor_sync(0xffffffffu, sumLo, 2);
    sumHi += __shfl_xor_sync(0xffffffffu, sumHi, 1);
    sumHi += __shfl_xor_sync(0xffffffffu, sumHi, 2);
    if ((lane & 3) == 0) {
        atomicAdd(&sWsum[rowE], sumLo);
        atomicAdd(&sWsum[rowE + 8], sumHi);
    }
    __syncthreads();
    if (tid < TR) {
        float t = sWsum[tid];
        sInv[tid] = (t > 0.f) ? (1.f / t) : 0.f;
    }
    cpwait0();             // no cp.async may still target the stage region
    __syncthreads();

    // ---- ctx partials -> dead stage region (per-warp 4KB buffers) ----
    {
        float* bufw = (float*)(smem + OFF_STAGE + w * 4096);
        const int r = lane >> 2, c2 = (lane & 3) << 1;
        #pragma unroll
        for (int n = 0; n < 8; n++) {
            *(float2*)&bufw[r * 64 + n * 8 + c2]       = make_float2(ctx[n][0], ctx[n][1]);
            *(float2*)&bufw[(r + 8) * 64 + n * 8 + c2] = make_float2(ctx[n][2], ctx[n][3]);
        }
    }
    __syncthreads();

    // ---- reduce across 8 col-warps + context write ----
    {
        const int rg2 = tid >> 8, rem = tid & 255;
        const int row = rem >> 4, d4 = rem & 15;
        const int grow = rg2 * 16 + row;
        if (grow < nrows) {
            float4 acc = {0.f, 0.f, 0.f, 0.f};
            #pragma unroll
            for (int cgi = 0; cgi < 8; cgi++) {
                float4 v = *(float4*)(smem + OFF_STAGE + (rg2 * 8 + cgi) * 4096
                                      + (row * 64 + d4 * 4) * 4);
                acc.x += v.x; acc.y += v.y; acc.z += v.z; acc.w += v.w;
            }
            float inv = sInv[grow];
            acc.x *= inv; acc.y *= inv; acc.z *= inv; acc.w *= inv;
            *(float4*)(out + ((size_t)b * S + sOrig[grow]) * D + d4 * 4) = acc;
        }
    }

    // ---- attn writeback: 2 rows/warp, pinv loaded once per column group ----
    {
        const int r0 = w * 2;
        const bool ok0 = (r0 < nrows), ok1 = (r0 + 1 < nrows);
        const float inv0 = ok0 ? sInv[r0] : 0.f;
        const float inv1 = ok1 ? sInv[r0 + 1] : 0.f;
        const __half* prow0 = &sPh[r0 * PP];
        const __half* prow1 = &sPh[(r0 + 1) * PP];
        float4* dst0 = ok0 ? (float4*)(out + (size_t)B * S * D
                                        + ((size_t)b * S + sOrig[r0]) * S) : nullptr;
        float4* dst1 = ok1 ? (float4*)(out + (size_t)B * S * D
                                        + ((size_t)b * S + sOrig[r0 + 1]) * S) : nullptr;
        if (ok0) {
            #pragma unroll 4
            for (int it = 0; it < 16; it++) {
                int cb = it * 32 + lane;
                int4 pv = ((const int4*)sPinv)[cb];
                float4 o0, o1;
                o0.x = (pv.x >= 0) ? __half2float(prow0[pv.x]) * inv0 : 0.f;
                o0.y = (pv.y >= 0) ? __half2float(prow0[pv.y]) * inv0 : 0.f;
                o0.z = (pv.z >= 0) ? __half2float(prow0[pv.z]) * inv0 : 0.f;
                o0.w = (pv.w >= 0) ? __half2float(prow0[pv.w]) * inv0 : 0.f;
                if (ok1) {
                    o1.x = (pv.x >= 0) ? __half2float(prow1[pv.x]) * inv1 : 0.f;
                    o1.y = (pv.y >= 0) ? __half2float(prow1[pv.y]) * inv1 : 0.f;
                    o1.z = (pv.z >= 0) ? __half2float(prow1[pv.z]) * inv1 : 0.f;
                    o1.w = (pv.w >= 0) ? __half2float(prow1[pv.w]) * inv1 : 0.f;
                }
                stcs4(dst0 + cb, o0);
                if (ok1) stcs4(dst1 + cb, o1);
            }
        }
    }
}

extern "C" void kernel_launch(void* const* d_in, const int* in_sizes, int n_in,
                              void* d_out, int out_size) {
    const float* Q = (const float*)d_in[0];
    const float* K = (const float*)d_in[1];
    const float* V = (const float*)d_in[2];
    const void*  M = d_in[3];
    float* out = (float*)d_out;

    cudaFuncSetAttribute(attn_kernel, cudaFuncAttributeMaxDynamicSharedMemorySize,
                         SMEM_BYTES);

    build_mask_kernel<<<B, 256>>>(M);
    preprocess_k_kernel<<<dim3(S / 64, B), 256>>>(K);
    preprocess_v_kernel<<<dim3(S / 64, B), 256>>>(V);
    attn_kernel<<<dim3(S / TR + 1, B), NTH, SMEM_BYTES>>>(Q, out);
}